// round 1
// baseline (speedup 1.0000x reference)
#include <cuda_runtime.h>
#include <math.h>

#define B_L   192
#define NVAL  325
#define NPAD  352
#define D     256
#define DPOS  64
#define KPROJ 320
#define HEADS 8
#define EDIM  32
#define BH    (B_L*HEADS)      /* 1536 */
#define NH    4
#define NB    22
#define NC    (NH*NB)          /* 88 */
#define BKTS  16
#define NS    (NH*NPAD)        /* 1408 */
#define MROWS (B_L*NPAD)       /* 67584 */

// ---------------- scratch (static device allocations; no cudaMalloc) ----------
__device__ float g_h    [B_L*NPAD*D];        // projected+padded hidden (pad rows = 0)
__device__ float g_qk   [BH*NPAD*EDIM];      // per-head qk
__device__ float g_v    [BH*NPAD*EDIM];      // per-head v
__device__ int   g_bucket [BH*NS];           // bucket id per (bh, hash*NPAD+n), in [0,88)
__device__ int   g_sticker[BH*NS];           // sorted order: slot -> item (hash*NPAD+n)
__device__ float g_o    [BH*NH*NPAD*EDIM];   // per-hash attention output (scattered)
__device__ float g_lse  [BH*NH*NPAD];        // per-hash logsumexp
__device__ float g_hcomb[B_L*NPAD*D];        // hash-combined, head-merged

// ---------------- generic 128x64 SGEMM, 8x4 per thread ------------------------
// MODE 0: h = [x|ste] @ w_proj + b_proj   (M=67584, K=320, N=256) -> g_h (pad rows 0)
// MODE 1: [qk|v] = g_h @ [w_qk|w_v]       (M=67584, K=256, N=512) -> g_qk/g_v
// MODE 2: out = g_hcomb @ w_out + b_out   (M=67584, K=256, N=256) -> d_out (n<325 only)
template<int MODE>
__global__ __launch_bounds__(256, 2)
void gemm_k(const float* __restrict__ P0, const float* __restrict__ P1,
            const float* __restrict__ W0, const float* __restrict__ W1,
            const float* __restrict__ bias, float* __restrict__ Cout)
{
    constexpr int BM = 128, BN = 64, BK = 16;
    constexpr int KDIM = (MODE == 0) ? KPROJ : 256;

    __shared__ float As[BK][BM + 4];
    __shared__ float Bs[BK][BN];

    const int tid = threadIdx.x;
    const int tx = tid & 15;        // output col group (4 cols)
    const int ty = tid >> 4;        // output row group (8 rows)
    const int bm = blockIdx.x * BM;
    const int bn = blockIdx.y * BN;

    const int lk = tid & 15;        // k lane for A loads
    const int lr = tid >> 4;        // row base for A loads
    const int bcol = tid & 63;      // col for B loads
    const int brow = tid >> 6;      // k base for B loads

    float acc[8][4];
#pragma unroll
    for (int i = 0; i < 8; i++)
#pragma unroll
        for (int j = 0; j < 4; j++) acc[i][j] = 0.f;

    // precompute per-row A addressing
    int baseA[8];
    int baseS[8];
    int validA[8];
#pragma unroll
    for (int p = 0; p < 8; p++) {
        int r = bm + lr + p * 16;
        if (MODE == 0) {
            int b_l = r / NPAD;
            int n   = r - b_l * NPAD;
            validA[p] = (n < NVAL);
            int rr = b_l * NVAL + n;
            baseA[p] = rr * D;
            baseS[p] = rr * DPOS;
        } else {
            baseA[p] = r * D;
            baseS[p] = 0;
            validA[p] = 1;
        }
    }

    for (int kt = 0; kt < KDIM; kt += BK) {
        // ---- load A tile (transposed into As[k][row]) ----
#pragma unroll
        for (int p = 0; p < 8; p++) {
            int kk = kt + lk;
            float v = 0.f;
            if (MODE == 0) {
                if (validA[p])
                    v = (kk < D) ? P0[baseA[p] + kk] : P1[baseS[p] + kk - D];
            } else if (MODE == 1) {
                v = g_h[baseA[p] + kk];
            } else {
                v = g_hcomb[baseA[p] + kk];
            }
            As[lk][lr + p * 16] = v;
        }
        // ---- load B tile ----
#pragma unroll
        for (int p = 0; p < 4; p++) {
            int k  = brow + p * 4;
            int kk = kt + k;
            int cg = bn + bcol;
            float v;
            if (MODE == 0) {
                v = W0[kk * D + cg];
            } else if (MODE == 1) {
                v = (cg < D) ? W0[kk * D + cg] : W1[kk * D + (cg - D)];
            } else {
                v = W0[kk * D + cg];
            }
            Bs[k][bcol] = v;
        }
        __syncthreads();

#pragma unroll
        for (int k = 0; k < BK; k++) {
            float4 b4 = *(const float4*)(&Bs[k][tx * 4]);
            float4 a0 = *(const float4*)(&As[k][ty * 8]);
            float4 a1 = *(const float4*)(&As[k][ty * 8 + 4]);
            float a[8] = {a0.x, a0.y, a0.z, a0.w, a1.x, a1.y, a1.z, a1.w};
            float b[4] = {b4.x, b4.y, b4.z, b4.w};
#pragma unroll
            for (int i = 0; i < 8; i++)
#pragma unroll
                for (int j = 0; j < 4; j++)
                    acc[i][j] += a[i] * b[j];
        }
        __syncthreads();
    }

    // ---- epilogue ----
#pragma unroll
    for (int i = 0; i < 8; i++) {
        int r = bm + ty * 8 + i;
        if (MODE == 0) {
            int n = r % NPAD;
#pragma unroll
            for (int j = 0; j < 4; j++) {
                int c = bn + tx * 4 + j;
                g_h[r * D + c] = (n < NVAL) ? (acc[i][j] + bias[c]) : 0.f;
            }
        } else if (MODE == 1) {
            int b_l = r / NPAD;
            int n   = r - b_l * NPAD;
#pragma unroll
            for (int j = 0; j < 4; j++) {
                int c = bn + tx * 4 + j;
                float v = acc[i][j];
                if (c < D) {
                    int head = c >> 5, e = c & 31;
                    g_qk[(((b_l << 3) + head) * NPAD + n) * EDIM + e] = v;
                } else {
                    int c2 = c - D;
                    int head = c2 >> 5, e = c2 & 31;
                    g_v[(((b_l << 3) + head) * NPAD + n) * EDIM + e] = v;
                }
            }
        } else {
            int b_l = r / NPAD;
            int n   = r - b_l * NPAD;
            if (n < NVAL) {
                int ro = (b_l * NVAL + n) * D;
#pragma unroll
                for (int j = 0; j < 4; j++) {
                    int c = bn + tx * 4 + j;
                    Cout[ro + c] = acc[i][j] + bias[c];
                }
            }
        }
    }
}

// ---------------- hashing: rot = qk @ rotations, argmax over [rot,-rot] -------
__global__ __launch_bounds__(256)
void hash_kernel(const float* __restrict__ rot)
{
    __shared__ float srot[EDIM * NH * (NB / 2)]; // 32*4*11 = 1408
    int tid = threadIdx.x;
    for (int i = tid; i < EDIM * NH * (NB / 2); i += blockDim.x) srot[i] = rot[i];
    __syncthreads();

    int gid = blockIdx.x * blockDim.x + tid;
    if (gid >= BH * NPAD) return;
    int bh = gid / NPAD;
    int n  = gid - bh * NPAD;

    float q[EDIM];
    const float* qp = &g_qk[(bh * NPAD + n) * EDIM];
#pragma unroll
    for (int e = 0; e < EDIM; e++) q[e] = qp[e];

    for (int h = 0; h < NH; h++) {
        float rv[NB / 2];
#pragma unroll
        for (int r = 0; r < NB / 2; r++) {
            float s = 0.f;
#pragma unroll
            for (int e = 0; e < EDIM; e++)
                s += q[e] * srot[e * (NH * (NB / 2)) + h * (NB / 2) + r];
            rv[r] = s;
        }
        // first-occurrence argmax over [rv, -rv] (matches jnp.argmax)
        float best = rv[0];
        int bi = 0;
#pragma unroll
        for (int r = 1; r < NB / 2; r++)
            if (rv[r] > best) { best = rv[r]; bi = r; }
#pragma unroll
        for (int r = 0; r < NB / 2; r++)
            if (-rv[r] > best) { best = -rv[r]; bi = r + NB / 2; }
        g_bucket[bh * NS + h * NPAD + n] = bi + h * NB;
    }
}

// ---------------- stable counting sort per bh (88 buckets, 1408 items) --------
__global__ __launch_bounds__(128)
void sort_kernel()
{
    const int bh  = blockIdx.x;
    const int tid = threadIdx.x;

    __shared__ unsigned short hist[128][89]; // [thread][bucket], padded stride 89
    __shared__ int sbuck[NS];
    __shared__ int base[NC];
    __shared__ int tot[NC];

    for (int i = tid; i < NS; i += 128) sbuck[i] = g_bucket[bh * NS + i];
    for (int b = 0; b < NC; b++) hist[tid][b] = 0;
    __syncthreads();

    // local histogram (items in position order -> stability)
#pragma unroll
    for (int k = 0; k < NS / 128; k++) {
        int i = tid * (NS / 128) + k;
        hist[tid][sbuck[i]]++;
    }
    __syncthreads();

    if (tid < NC) {
        int s = 0;
        for (int t = 0; t < 128; t++) s += hist[t][tid];
        tot[tid] = s;
    }
    __syncthreads();
    if (tid == 0) {
        int run = 0;
        for (int b = 0; b < NC; b++) { base[b] = run; run += tot[b]; }
    }
    __syncthreads();
    if (tid < NC) {
        int run = base[tid];
        for (int t = 0; t < 128; t++) {
            int c = hist[t][tid];
            hist[t][tid] = (unsigned short)run;
            run += c;
        }
    }
    __syncthreads();

#pragma unroll
    for (int k = 0; k < NS / 128; k++) {
        int i = tid * (NS / 128) + k;
        int b = sbuck[i];
        int pos = hist[tid][b]++;
        g_sticker[bh * NS + pos] = i;
    }
}

// ---------------- chunked attention: 16 queries x 32 keys per block -----------
__global__ __launch_bounds__(512)
void attn_kernel()
{
    const int c  = blockIdx.x;   // chunk 0..87
    const int bh = blockIdx.y;   // 0..1535

    __shared__ float kq[32][33];
    __shared__ float vv[32][33];
    __shared__ float rn[32];
    __shared__ int   nn[32];
    __shared__ int   hh[32];

    const int tid  = threadIdx.x;
    const int warp = tid >> 5;
    const int lane = tid & 31;

    if (tid < 32) {
        int cj   = (tid < BKTS) ? c : (c + NC - 1) % NC;   // current / rolled-prev chunk
        int slot = cj * BKTS + (tid & (BKTS - 1));
        int item = g_sticker[bh * NS + slot];
        int n    = item % NPAD;
        nn[tid] = n;
        hh[tid] = item / NPAD;
    }
    __syncthreads();

    for (int idx = tid; idx < 32 * EDIM; idx += 512) {
        int j = idx >> 5, e = idx & 31;
        int off = (bh * NPAD + nn[j]) * EDIM + e;
        kq[j][e] = g_qk[off];
        vv[j][e] = g_v[off];
    }
    __syncthreads();

    if (tid < 32) {
        float s = 0.f;
#pragma unroll
        for (int e = 0; e < EDIM; e++) { float x = kq[tid][e]; s += x * x; }
        s = sqrtf(s);
        rn[tid] = 1.0f / fmaxf(s, 1e-12f);
    }
    __syncthreads();

    const int i = warp;   // query index (0..15)
    const int j = lane;   // key index (0..31)

    float d = 0.f;
#pragma unroll
    for (int e = 0; e < EDIM; e++) d += kq[i][e] * kq[j][e];
    d = d * rn[j] * 0.17677669529663687f;   // * E^-0.5 with normalized key
    if (nn[i] == nn[j]) d = -50000.0f;      // self-attention mask

    float m = d;
#pragma unroll
    for (int o = 16; o > 0; o >>= 1) m = fmaxf(m, __shfl_xor_sync(0xffffffffu, m, o));
    float ex = expf(d - m);
    float sum = ex;
#pragma unroll
    for (int o = 16; o > 0; o >>= 1) sum += __shfl_xor_sync(0xffffffffu, sum, o);
    float lse = m + logf(sum);
    float p = ex / sum;

    float accv = 0.f;
#pragma unroll
    for (int jj = 0; jj < 32; jj++) {
        float pj = __shfl_sync(0xffffffffu, p, jj);
        accv += pj * vv[jj][lane];
    }

    int n_i = nn[i], h_i = hh[i];
    g_o[((bh * NH + h_i) * NPAD + n_i) * EDIM + lane] = accv;
    if (lane == 0) g_lse[(bh * NH + h_i) * NPAD + n_i] = lse;
}

// ---------------- combine hashes: softmax over per-hash lse -------------------
__global__ __launch_bounds__(256)
void combine_kernel()
{
    int gid  = blockIdx.x * blockDim.x + threadIdx.x;
    int wid  = gid >> 5;
    int lane = gid & 31;
    if (wid >= BH * NPAD) return;
    int bh = wid / NPAD;
    int n  = wid - bh * NPAD;

    float l0 = g_lse[(bh * NH + 0) * NPAD + n];
    float l1 = g_lse[(bh * NH + 1) * NPAD + n];
    float l2 = g_lse[(bh * NH + 2) * NPAD + n];
    float l3 = g_lse[(bh * NH + 3) * NPAD + n];
    float m = fmaxf(fmaxf(l0, l1), fmaxf(l2, l3));
    float e0 = expf(l0 - m), e1 = expf(l1 - m), e2 = expf(l2 - m), e3 = expf(l3 - m);
    float inv = 1.0f / (e0 + e1 + e2 + e3);

    float acc =
        e0 * inv * g_o[((bh * NH + 0) * NPAD + n) * EDIM + lane] +
        e1 * inv * g_o[((bh * NH + 1) * NPAD + n) * EDIM + lane] +
        e2 * inv * g_o[((bh * NH + 2) * NPAD + n) * EDIM + lane] +
        e3 * inv * g_o[((bh * NH + 3) * NPAD + n) * EDIM + lane];

    int b_l = bh >> 3, head = bh & 7;
    g_hcomb[(b_l * NPAD + n) * D + head * EDIM + lane] = acc;
}

// ---------------- launch ------------------------------------------------------
extern "C" void kernel_launch(void* const* d_in, const int* in_sizes, int n_in,
                              void* d_out, int out_size)
{
    const float* x      = (const float*)d_in[0];
    const float* ste    = (const float*)d_in[1];
    const float* w_proj = (const float*)d_in[2];
    const float* b_proj = (const float*)d_in[3];
    const float* w_qk   = (const float*)d_in[4];
    const float* w_v    = (const float*)d_in[5];
    const float* w_out  = (const float*)d_in[6];
    const float* b_out  = (const float*)d_in[7];
    const float* rots   = (const float*)d_in[8];
    float* out = (float*)d_out;

    // 1. projection (+pad rows zeroed)
    gemm_k<0><<<dim3(MROWS / 128, 256 / 64), 256>>>(x, ste, w_proj, nullptr, b_proj, nullptr);
    // 2. fused qk / v projection
    gemm_k<1><<<dim3(MROWS / 128, 512 / 64), 256>>>(nullptr, nullptr, w_qk, w_v, nullptr, nullptr);
    // 3. LSH bucketing
    hash_kernel<<<(BH * NPAD + 255) / 256, 256>>>(rots);
    // 4. stable counting sort per (batch*head)
    sort_kernel<<<BH, 128>>>();
    // 5. bucket-chunk attention with scatter
    attn_kernel<<<dim3(NC, BH), 512>>>();
    // 6. combine over hash rounds
    combine_kernel<<<(BH * NPAD * 32) / 256, 256>>>();
    // 7. output projection (valid rows only)
    gemm_k<2><<<dim3(MROWS / 128, 256 / 64), 256>>>(nullptr, nullptr, w_out, nullptr, b_out, out);
}

// round 2
// speedup vs baseline: 1.1304x; 1.1304x over previous
#include <cuda_runtime.h>
#include <math.h>

#define B_L   192
#define NVAL  325
#define NPAD  352
#define D     256
#define DPOS  64
#define KPROJ 320
#define HEADS 8
#define EDIM  32
#define BH    (B_L*HEADS)      /* 1536 */
#define NH    4
#define NB    22
#define NC    (NH*NB)          /* 88 */
#define BKTS  16
#define NS    (NH*NPAD)        /* 1408 */
#define MROWS (B_L*NPAD)       /* 67584 */

// ---------------- scratch (static device allocations; no cudaMalloc) ----------
__device__ __align__(16) float g_h    [B_L*NPAD*D];
__device__ __align__(16) float g_qk   [BH*NPAD*EDIM];
__device__ __align__(16) float g_v    [BH*NPAD*EDIM];
__device__ int   g_bucket [BH*NS];
__device__ int   g_sticker[BH*NS];
__device__ __align__(16) float g_o    [BH*NH*NPAD*EDIM];
__device__ float g_lse  [BH*NH*NPAD];
__device__ __align__(16) float g_hcomb[B_L*NPAD*D];

// ---------------- 128x128 SGEMM, BK=8, 8x8/thread, double-buffered ------------
// MODE 0: h = [x|ste] @ w_proj + b_proj   (M=67584, K=320, N=256) -> g_h (pad rows 0)
// MODE 1: [qk|v] = g_h @ [w_qk|w_v]       (M=67584, K=256, N=512) -> g_qk/g_v
// MODE 2: out = g_hcomb @ w_out + b_out   (M=67584, K=256, N=256) -> d_out (n<325 only)
template<int MODE>
__global__ __launch_bounds__(256, 2)
void gemm_k(const float* __restrict__ P0, const float* __restrict__ P1,
            const float* __restrict__ W0, const float* __restrict__ W1,
            const float* __restrict__ bias, float* __restrict__ Cout)
{
    constexpr int BM = 128, BN = 128, BK = 8;
    constexpr int KDIM = (MODE == 0) ? KPROJ : 256;
    constexpr int NT   = KDIM / BK;
    constexpr int LDA  = BM + 4;   // pad: kills STS bank conflicts, keeps 16B align (132*4=528=33*16)

    __shared__ float As[2][BK][LDA];
    __shared__ float Bs[2][BK][BN];

    const int tid = threadIdx.x;
    const int bm  = blockIdx.x * BM;
    const int bn  = blockIdx.y * BN;

    // A-load mapping: thread loads float4 at (row=tid>>1, k=kt + (tid&1)*4)
    const int arow  = tid >> 1;
    const int akoff = (tid & 1) * 4;
    // B-load mapping: thread loads float4 at (k=tid>>5, col=(tid&31)*4)
    const int bk    = tid >> 5;
    const int bcol  = (tid & 31) * 4;

    // resolve A source pointer / validity
    const int r = bm + arow;
    long baseA, baseS = 0;
    bool validA = true;
    if (MODE == 0) {
        int b_l = r / NPAD;
        int n   = r - b_l * NPAD;
        validA  = (n < NVAL);
        long rr = (long)b_l * NVAL + n;
        baseA = rr * D;
        baseS = rr * DPOS;
    } else {
        baseA = (long)r * D;
    }

    // resolve B source pointer (whole 128-col block lives in one matrix)
    const float* Wp;
    int wcolbase;
    if (MODE == 1 && bn >= 256) { Wp = W1; wcolbase = bn - 256; }
    else                         { Wp = W0; wcolbase = bn; }

    float4 aReg, bReg;

    auto load_gmem = [&](int kt) {
        int kk = kt + akoff;
        if (MODE == 0) {
            if (!validA) aReg = make_float4(0.f, 0.f, 0.f, 0.f);
            else if (kk < D) aReg = *(const float4*)(P0 + baseA + kk);
            else             aReg = *(const float4*)(P1 + baseS + (kk - D));
        } else if (MODE == 1) {
            aReg = *(const float4*)(g_h + baseA + kk);
        } else {
            aReg = *(const float4*)(g_hcomb + baseA + kk);
        }
        bReg = *(const float4*)(Wp + (long)(kt + bk) * D + wcolbase + bcol);
    };
    auto store_smem = [&](int buf) {
        As[buf][akoff + 0][arow] = aReg.x;
        As[buf][akoff + 1][arow] = aReg.y;
        As[buf][akoff + 2][arow] = aReg.z;
        As[buf][akoff + 3][arow] = aReg.w;
        *(float4*)(&Bs[buf][bk][bcol]) = bReg;
    };

    float acc[8][8];
#pragma unroll
    for (int i = 0; i < 8; i++)
#pragma unroll
        for (int j = 0; j < 8; j++) acc[i][j] = 0.f;

    const int ty = (tid >> 4) * 8;   // row base within tile
    const int tx = (tid & 15) * 8;   // col base within tile

    load_gmem(0);
    store_smem(0);
    __syncthreads();

    int buf = 0;
    for (int t = 0; t < NT; ++t) {
        if (t + 1 < NT) load_gmem((t + 1) * BK);
#pragma unroll
        for (int k = 0; k < BK; k++) {
            float4 a0 = *(const float4*)(&As[buf][k][ty]);
            float4 a1 = *(const float4*)(&As[buf][k][ty + 4]);
            float4 b0 = *(const float4*)(&Bs[buf][k][tx]);
            float4 b1 = *(const float4*)(&Bs[buf][k][tx + 4]);
            float a[8] = {a0.x, a0.y, a0.z, a0.w, a1.x, a1.y, a1.z, a1.w};
            float b[8] = {b0.x, b0.y, b0.z, b0.w, b1.x, b1.y, b1.z, b1.w};
#pragma unroll
            for (int i = 0; i < 8; i++)
#pragma unroll
                for (int j = 0; j < 8; j++)
                    acc[i][j] += a[i] * b[j];
        }
        if (t + 1 < NT) {
            store_smem(buf ^ 1);
            __syncthreads();
            buf ^= 1;
        }
    }

    // ---- epilogue ----
#pragma unroll
    for (int i = 0; i < 8; i++) {
        int ro = bm + ty + i;
        if (MODE == 0) {
            int n = ro % NPAD;
            float4 v0, v1;
            if (n < NVAL) {
                v0 = make_float4(acc[i][0] + bias[bn + tx + 0], acc[i][1] + bias[bn + tx + 1],
                                 acc[i][2] + bias[bn + tx + 2], acc[i][3] + bias[bn + tx + 3]);
                v1 = make_float4(acc[i][4] + bias[bn + tx + 4], acc[i][5] + bias[bn + tx + 5],
                                 acc[i][6] + bias[bn + tx + 6], acc[i][7] + bias[bn + tx + 7]);
            } else {
                v0 = make_float4(0.f, 0.f, 0.f, 0.f);
                v1 = v0;
            }
            *(float4*)(g_h + (long)ro * D + bn + tx)     = v0;
            *(float4*)(g_h + (long)ro * D + bn + tx + 4) = v1;
        } else if (MODE == 1) {
            int b_l = ro / NPAD;
            int n   = ro - b_l * NPAD;
            int c   = bn + tx;            // aligned to 8; one head per 8-col group
            float* dst;
            int cc = c, e;
            if (cc < D) { int head = cc >> 5; e = cc & 31;
                dst = g_qk + ((long)((b_l << 3) + head) * NPAD + n) * EDIM + e; }
            else        { cc -= D; int head = cc >> 5; e = cc & 31;
                dst = g_v  + ((long)((b_l << 3) + head) * NPAD + n) * EDIM + e; }
            *(float4*)(dst)     = make_float4(acc[i][0], acc[i][1], acc[i][2], acc[i][3]);
            *(float4*)(dst + 4) = make_float4(acc[i][4], acc[i][5], acc[i][6], acc[i][7]);
        } else {
            int b_l = ro / NPAD;
            int n   = ro - b_l * NPAD;
            if (n < NVAL) {
                long off = ((long)b_l * NVAL + n) * D + bn + tx;
                *(float4*)(Cout + off) =
                    make_float4(acc[i][0] + bias[bn + tx + 0], acc[i][1] + bias[bn + tx + 1],
                                acc[i][2] + bias[bn + tx + 2], acc[i][3] + bias[bn + tx + 3]);
                *(float4*)(Cout + off + 4) =
                    make_float4(acc[i][4] + bias[bn + tx + 4], acc[i][5] + bias[bn + tx + 5],
                                acc[i][6] + bias[bn + tx + 6], acc[i][7] + bias[bn + tx + 7]);
            }
        }
    }
}

// ---------------- hashing: rot = qk @ rotations, argmax over [rot,-rot] -------
__global__ __launch_bounds__(256)
void hash_kernel(const float* __restrict__ rot)
{
    __shared__ float srot[EDIM * NH * (NB / 2)];
    int tid = threadIdx.x;
    for (int i = tid; i < EDIM * NH * (NB / 2); i += blockDim.x) srot[i] = rot[i];
    __syncthreads();

    int gid = blockIdx.x * blockDim.x + tid;
    if (gid >= BH * NPAD) return;
    int bh = gid / NPAD;
    int n  = gid - bh * NPAD;

    float q[EDIM];
    const float* qp = &g_qk[(bh * NPAD + n) * EDIM];
#pragma unroll
    for (int e = 0; e < EDIM; e++) q[e] = qp[e];

    for (int h = 0; h < NH; h++) {
        float rv[NB / 2];
#pragma unroll
        for (int r = 0; r < NB / 2; r++) {
            float s = 0.f;
#pragma unroll
            for (int e = 0; e < EDIM; e++)
                s += q[e] * srot[e * (NH * (NB / 2)) + h * (NB / 2) + r];
            rv[r] = s;
        }
        float best = rv[0];
        int bi = 0;
#pragma unroll
        for (int r = 1; r < NB / 2; r++)
            if (rv[r] > best) { best = rv[r]; bi = r; }
#pragma unroll
        for (int r = 0; r < NB / 2; r++)
            if (-rv[r] > best) { best = -rv[r]; bi = r + NB / 2; }
        g_bucket[bh * NS + h * NPAD + n] = bi + h * NB;
    }
}

// ---------------- stable counting sort per bh (88 buckets, 1408 items) --------
__global__ __launch_bounds__(128)
void sort_kernel()
{
    const int bh  = blockIdx.x;
    const int tid = threadIdx.x;

    __shared__ unsigned short hist[128][89];
    __shared__ int sbuck[NS];
    __shared__ int base[NC];
    __shared__ int tot[NC];

    for (int i = tid; i < NS; i += 128) sbuck[i] = g_bucket[bh * NS + i];
    for (int b = 0; b < NC; b++) hist[tid][b] = 0;
    __syncthreads();

#pragma unroll
    for (int k = 0; k < NS / 128; k++) {
        int i = tid * (NS / 128) + k;
        hist[tid][sbuck[i]]++;
    }
    __syncthreads();

    if (tid < NC) {
        int s = 0;
        for (int t = 0; t < 128; t++) s += hist[t][tid];
        tot[tid] = s;
    }
    __syncthreads();
    if (tid == 0) {
        int run = 0;
        for (int b = 0; b < NC; b++) { base[b] = run; run += tot[b]; }
    }
    __syncthreads();
    if (tid < NC) {
        int run = base[tid];
        for (int t = 0; t < 128; t++) {
            int c = hist[t][tid];
            hist[t][tid] = (unsigned short)run;
            run += c;
        }
    }
    __syncthreads();

#pragma unroll
    for (int k = 0; k < NS / 128; k++) {
        int i = tid * (NS / 128) + k;
        int b = sbuck[i];
        int pos = hist[tid][b]++;
        g_sticker[bh * NS + pos] = i;
    }
}

// ---------------- chunked attention: 16 queries x 32 keys per block -----------
__global__ __launch_bounds__(512)
void attn_kernel()
{
    const int c  = blockIdx.x;
    const int bh = blockIdx.y;

    __shared__ float kq[32][33];
    __shared__ float vv[32][33];
    __shared__ float rn[32];
    __shared__ int   nn[32];
    __shared__ int   hh[32];

    const int tid  = threadIdx.x;
    const int warp = tid >> 5;
    const int lane = tid & 31;

    if (tid < 32) {
        int cj   = (tid < BKTS) ? c : (c + NC - 1) % NC;
        int slot = cj * BKTS + (tid & (BKTS - 1));
        int item = g_sticker[bh * NS + slot];
        int n    = item % NPAD;
        nn[tid] = n;
        hh[tid] = item / NPAD;
    }
    __syncthreads();

    for (int idx = tid; idx < 32 * EDIM; idx += 512) {
        int j = idx >> 5, e = idx & 31;
        int off = (bh * NPAD + nn[j]) * EDIM + e;
        kq[j][e] = g_qk[off];
        vv[j][e] = g_v[off];
    }
    __syncthreads();

    if (tid < 32) {
        float s = 0.f;
#pragma unroll
        for (int e = 0; e < EDIM; e++) { float x = kq[tid][e]; s += x * x; }
        s = sqrtf(s);
        rn[tid] = 1.0f / fmaxf(s, 1e-12f);
    }
    __syncthreads();

    const int i = warp;
    const int j = lane;

    float d = 0.f;
#pragma unroll
    for (int e = 0; e < EDIM; e++) d += kq[i][e] * kq[j][e];
    d = d * rn[j] * 0.17677669529663687f;
    if (nn[i] == nn[j]) d = -50000.0f;

    float m = d;
#pragma unroll
    for (int o = 16; o > 0; o >>= 1) m = fmaxf(m, __shfl_xor_sync(0xffffffffu, m, o));
    float ex = expf(d - m);
    float sum = ex;
#pragma unroll
    for (int o = 16; o > 0; o >>= 1) sum += __shfl_xor_sync(0xffffffffu, sum, o);
    float lse = m + logf(sum);
    float p = ex / sum;

    float accv = 0.f;
#pragma unroll
    for (int jj = 0; jj < 32; jj++) {
        float pj = __shfl_sync(0xffffffffu, p, jj);
        accv += pj * vv[jj][lane];
    }

    int n_i = nn[i], h_i = hh[i];
    g_o[((bh * NH + h_i) * NPAD + n_i) * EDIM + lane] = accv;
    if (lane == 0) g_lse[(bh * NH + h_i) * NPAD + n_i] = lse;
}

// ---------------- combine hashes: softmax over per-hash lse -------------------
__global__ __launch_bounds__(256)
void combine_kernel()
{
    int gid  = blockIdx.x * blockDim.x + threadIdx.x;
    int wid  = gid >> 5;
    int lane = gid & 31;
    if (wid >= BH * NPAD) return;
    int bh = wid / NPAD;
    int n  = wid - bh * NPAD;

    float l0 = g_lse[(bh * NH + 0) * NPAD + n];
    float l1 = g_lse[(bh * NH + 1) * NPAD + n];
    float l2 = g_lse[(bh * NH + 2) * NPAD + n];
    float l3 = g_lse[(bh * NH + 3) * NPAD + n];
    float m = fmaxf(fmaxf(l0, l1), fmaxf(l2, l3));
    float e0 = expf(l0 - m), e1 = expf(l1 - m), e2 = expf(l2 - m), e3 = expf(l3 - m);
    float inv = 1.0f / (e0 + e1 + e2 + e3);

    float acc =
        e0 * inv * g_o[((bh * NH + 0) * NPAD + n) * EDIM + lane] +
        e1 * inv * g_o[((bh * NH + 1) * NPAD + n) * EDIM + lane] +
        e2 * inv * g_o[((bh * NH + 2) * NPAD + n) * EDIM + lane] +
        e3 * inv * g_o[((bh * NH + 3) * NPAD + n) * EDIM + lane];

    int b_l = bh >> 3, head = bh & 7;
    g_hcomb[(b_l * NPAD + n) * D + head * EDIM + lane] = acc;
}

// ---------------- launch ------------------------------------------------------
extern "C" void kernel_launch(void* const* d_in, const int* in_sizes, int n_in,
                              void* d_out, int out_size)
{
    const float* x      = (const float*)d_in[0];
    const float* ste    = (const float*)d_in[1];
    const float* w_proj = (const float*)d_in[2];
    const float* b_proj = (const float*)d_in[3];
    const float* w_qk   = (const float*)d_in[4];
    const float* w_v    = (const float*)d_in[5];
    const float* w_out  = (const float*)d_in[6];
    const float* b_out  = (const float*)d_in[7];
    const float* rots   = (const float*)d_in[8];
    float* out = (float*)d_out;

    gemm_k<0><<<dim3(MROWS / 128, 256 / 128), 256>>>(x, ste, w_proj, nullptr, b_proj, nullptr);
    gemm_k<1><<<dim3(MROWS / 128, 512 / 128), 256>>>(nullptr, nullptr, w_qk, w_v, nullptr, nullptr);
    hash_kernel<<<(BH * NPAD + 255) / 256, 256>>>(rots);
    sort_kernel<<<BH, 128>>>();
    attn_kernel<<<dim3(NC, BH), 512>>>();
    combine_kernel<<<(BH * NPAD * 32) / 256, 256>>>();
    gemm_k<2><<<dim3(MROWS / 128, 256 / 128), 256>>>(nullptr, nullptr, w_out, nullptr, b_out, out);
}

// round 3
// speedup vs baseline: 1.1885x; 1.0514x over previous
#include <cuda_runtime.h>
#include <math.h>

#define B_L   192
#define NVAL  325
#define NPAD  352
#define D     256
#define DPOS  64
#define KPROJ 320
#define HEADS 8
#define EDIM  32
#define BH    (B_L*HEADS)      /* 1536 */
#define NH    4
#define NB    22
#define NC    (NH*NB)          /* 88 */
#define BKTS  16
#define NS    (NH*NPAD)        /* 1408 */
#define MROWS (B_L*NPAD)       /* 67584 */

typedef unsigned long long u64;

__device__ __forceinline__ u64 pack2(float x, float y) {
    u64 r; asm("mov.b64 %0,{%1,%2};" : "=l"(r) : "f"(x), "f"(y)); return r;
}
__device__ __forceinline__ void unpack2(u64 v, float& x, float& y) {
    asm("mov.b64 {%0,%1},%2;" : "=f"(x), "=f"(y) : "l"(v));
}
__device__ __forceinline__ u64 fma2(u64 a, u64 b, u64 c) {
    u64 d; asm("fma.rn.f32x2 %0,%1,%2,%3;" : "=l"(d) : "l"(a), "l"(b), "l"(c)); return d;
}

// ---------------- scratch (static device allocations; no cudaMalloc) ----------
__device__ __align__(16) float g_h    [B_L*NPAD*D];
__device__ __align__(16) float g_qk   [BH*NPAD*EDIM];
__device__ __align__(16) float g_v    [BH*NPAD*EDIM];
__device__ int   g_bucket [BH*NS];
__device__ int   g_sticker[BH*NS];
__device__ __align__(16) float g_o    [BH*NH*NPAD*EDIM];
__device__ float g_lse  [BH*NH*NPAD];
__device__ __align__(16) float g_hcomb[B_L*NPAD*D];

// ---------------- 128x128 SGEMM, BK=8, 8x8/thread, FFMA2 inner loop -----------
// MODE 0: h = [x|ste] @ w_proj + b_proj   (M=67584, K=320, N=256) -> g_h (pad rows 0)
// MODE 1: [qk|v] = g_h @ [w_qk|w_v]       (M=67584, K=256, N=512) -> g_qk/g_v
// MODE 2: out = g_hcomb @ w_out + b_out   (M=67584, K=256, N=256) -> d_out (n<325 only)
template<int MODE>
__global__ __launch_bounds__(256, 2)
void gemm_k(const float* __restrict__ P0, const float* __restrict__ P1,
            const float* __restrict__ W0, const float* __restrict__ W1,
            const float* __restrict__ bias, float* __restrict__ Cout)
{
    constexpr int BM = 128, BN = 128, BK = 8;
    constexpr int KDIM = (MODE == 0) ? KPROJ : 256;
    constexpr int NT   = KDIM / BK;
    constexpr int LDA  = BM + 4;

    __shared__ float As[2][BK][LDA];
    __shared__ float Bs[2][BK][BN];

    const int tid = threadIdx.x;
    const int bm  = blockIdx.x * BM;
    const int bn  = blockIdx.y * BN;

    const int arow  = tid >> 1;
    const int akoff = (tid & 1) * 4;
    const int bk    = tid >> 5;
    const int bcol  = (tid & 31) * 4;

    const int r = bm + arow;
    long baseA, baseS = 0;
    bool validA = true;
    if (MODE == 0) {
        int b_l = r / NPAD;
        int n   = r - b_l * NPAD;
        validA  = (n < NVAL);
        long rr = (long)b_l * NVAL + n;
        baseA = rr * D;
        baseS = rr * DPOS;
    } else {
        baseA = (long)r * D;
    }

    const float* Wp;
    int wcolbase;
    if (MODE == 1 && bn >= 256) { Wp = W1; wcolbase = bn - 256; }
    else                         { Wp = W0; wcolbase = bn; }

    float4 aReg, bReg;

    auto load_gmem = [&](int kt) {
        int kk = kt + akoff;
        if (MODE == 0) {
            if (!validA) aReg = make_float4(0.f, 0.f, 0.f, 0.f);
            else if (kk < D) aReg = *(const float4*)(P0 + baseA + kk);
            else             aReg = *(const float4*)(P1 + baseS + (kk - D));
        } else if (MODE == 1) {
            aReg = *(const float4*)(g_h + baseA + kk);
        } else {
            aReg = *(const float4*)(g_hcomb + baseA + kk);
        }
        bReg = *(const float4*)(Wp + (long)(kt + bk) * D + wcolbase + bcol);
    };
    auto store_smem = [&](int buf) {
        As[buf][akoff + 0][arow] = aReg.x;
        As[buf][akoff + 1][arow] = aReg.y;
        As[buf][akoff + 2][arow] = aReg.z;
        As[buf][akoff + 3][arow] = aReg.w;
        *(float4*)(&Bs[buf][bk][bcol]) = bReg;
    };

    // packed accumulators: acc2[i][q] = {acc[i][2q], acc[i][2q+1]}
    u64 acc2[8][4];
#pragma unroll
    for (int i = 0; i < 8; i++)
#pragma unroll
        for (int q = 0; q < 4; q++) acc2[i][q] = 0ULL;

    const int ty = (tid >> 4) * 8;
    const int tx = (tid & 15) * 8;

    load_gmem(0);
    store_smem(0);
    __syncthreads();

    int buf = 0;
    for (int t = 0; t < NT; ++t) {
        if (t + 1 < NT) load_gmem((t + 1) * BK);
#pragma unroll
        for (int k = 0; k < BK; k++) {
            float4 a0 = *(const float4*)(&As[buf][k][ty]);
            float4 a1 = *(const float4*)(&As[buf][k][ty + 4]);
            // b pairs directly from SMEM (consecutive columns -> low/high lanes)
            u64 bb0 = *(const u64*)(&Bs[buf][k][tx + 0]);
            u64 bb1 = *(const u64*)(&Bs[buf][k][tx + 2]);
            u64 bb2 = *(const u64*)(&Bs[buf][k][tx + 4]);
            u64 bb3 = *(const u64*)(&Bs[buf][k][tx + 6]);
            float a[8] = {a0.x, a0.y, a0.z, a0.w, a1.x, a1.y, a1.z, a1.w};
#pragma unroll
            for (int i = 0; i < 8; i++) {
                u64 ap = pack2(a[i], a[i]);
                acc2[i][0] = fma2(ap, bb0, acc2[i][0]);
                acc2[i][1] = fma2(ap, bb1, acc2[i][1]);
                acc2[i][2] = fma2(ap, bb2, acc2[i][2]);
                acc2[i][3] = fma2(ap, bb3, acc2[i][3]);
            }
        }
        if (t + 1 < NT) {
            store_smem(buf ^ 1);
            __syncthreads();
            buf ^= 1;
        }
    }

    // ---- epilogue ----
#pragma unroll
    for (int i = 0; i < 8; i++) {
        int ro = bm + ty + i;
        float c[8];
#pragma unroll
        for (int q = 0; q < 4; q++) unpack2(acc2[i][q], c[2 * q], c[2 * q + 1]);

        if (MODE == 0) {
            int n = ro % NPAD;
            float4 v0, v1;
            if (n < NVAL) {
                v0 = make_float4(c[0] + bias[bn + tx + 0], c[1] + bias[bn + tx + 1],
                                 c[2] + bias[bn + tx + 2], c[3] + bias[bn + tx + 3]);
                v1 = make_float4(c[4] + bias[bn + tx + 4], c[5] + bias[bn + tx + 5],
                                 c[6] + bias[bn + tx + 6], c[7] + bias[bn + tx + 7]);
            } else {
                v0 = make_float4(0.f, 0.f, 0.f, 0.f);
                v1 = v0;
            }
            *(float4*)(g_h + (long)ro * D + bn + tx)     = v0;
            *(float4*)(g_h + (long)ro * D + bn + tx + 4) = v1;
        } else if (MODE == 1) {
            int b_l = ro / NPAD;
            int n   = ro - b_l * NPAD;
            int cidx = bn + tx;
            float* dst;
            int cc = cidx, e;
            if (cc < D) { int head = cc >> 5; e = cc & 31;
                dst = g_qk + ((long)((b_l << 3) + head) * NPAD + n) * EDIM + e; }
            else        { cc -= D; int head = cc >> 5; e = cc & 31;
                dst = g_v  + ((long)((b_l << 3) + head) * NPAD + n) * EDIM + e; }
            *(float4*)(dst)     = make_float4(c[0], c[1], c[2], c[3]);
            *(float4*)(dst + 4) = make_float4(c[4], c[5], c[6], c[7]);
        } else {
            int b_l = ro / NPAD;
            int n   = ro - b_l * NPAD;
            if (n < NVAL) {
                long off = ((long)b_l * NVAL + n) * D + bn + tx;
                *(float4*)(Cout + off) =
                    make_float4(c[0] + bias[bn + tx + 0], c[1] + bias[bn + tx + 1],
                                c[2] + bias[bn + tx + 2], c[3] + bias[bn + tx + 3]);
                *(float4*)(Cout + off + 4) =
                    make_float4(c[4] + bias[bn + tx + 4], c[5] + bias[bn + tx + 5],
                                c[6] + bias[bn + tx + 6], c[7] + bias[bn + tx + 7]);
            }
        }
    }
}

// ---------------- hashing: rot = qk @ rotations, argmax over [rot,-rot] -------
// rv[r] chains over e are kept in the exact same order as before (bit-identical
// argmax inputs); rotation pairs (2r, 2r+1) are packed, 12th column zero-padded.
__global__ __launch_bounds__(256)
void hash_kernel(const float* __restrict__ rot)
{
    __shared__ u64 srot2[EDIM][NH][6];   // packed pairs, 6KB
    int tid = threadIdx.x;
    for (int i = tid; i < EDIM * NH * 6; i += blockDim.x) {
        int e  = i / (NH * 6);
        int h  = (i / 6) % NH;
        int rr = i % 6;
        int r0 = 2 * rr, r1 = 2 * rr + 1;
        float x = (r0 < NB / 2) ? rot[(e * NH + h) * (NB / 2) + r0] : 0.f;
        float y = (r1 < NB / 2) ? rot[(e * NH + h) * (NB / 2) + r1] : 0.f;
        srot2[e][h][rr] = pack2(x, y);
    }
    __syncthreads();

    int gid = blockIdx.x * blockDim.x + tid;
    if (gid >= BH * NPAD) return;
    int bh = gid / NPAD;
    int n  = gid - bh * NPAD;

    float q[EDIM];
    const float* qp = &g_qk[(bh * NPAD + n) * EDIM];
#pragma unroll
    for (int e = 0; e < EDIM; e += 4) {
        float4 t = *(const float4*)(qp + e);
        q[e] = t.x; q[e + 1] = t.y; q[e + 2] = t.z; q[e + 3] = t.w;
    }

    for (int h = 0; h < NH; h++) {
        u64 s2[6];
#pragma unroll
        for (int rr = 0; rr < 6; rr++) s2[rr] = 0ULL;
#pragma unroll
        for (int e = 0; e < EDIM; e++) {
            u64 qq = pack2(q[e], q[e]);
#pragma unroll
            for (int rr = 0; rr < 6; rr++)
                s2[rr] = fma2(qq, srot2[e][h][rr], s2[rr]);
        }
        float rv[12];
#pragma unroll
        for (int rr = 0; rr < 6; rr++) unpack2(s2[rr], rv[2 * rr], rv[2 * rr + 1]);

        float best = rv[0];
        int bi = 0;
#pragma unroll
        for (int r = 1; r < NB / 2; r++)
            if (rv[r] > best) { best = rv[r]; bi = r; }
#pragma unroll
        for (int r = 0; r < NB / 2; r++)
            if (-rv[r] > best) { best = -rv[r]; bi = r + NB / 2; }
        g_bucket[bh * NS + h * NPAD + n] = bi + h * NB;
    }
}

// ---------------- stable counting sort per bh (88 buckets, 1408 items) --------
__global__ __launch_bounds__(128)
void sort_kernel()
{
    const int bh  = blockIdx.x;
    const int tid = threadIdx.x;

    __shared__ unsigned short hist[128][89];
    __shared__ int sbuck[NS];
    __shared__ int base[NC];
    __shared__ int tot[NC];

    for (int i = tid; i < NS; i += 128) sbuck[i] = g_bucket[bh * NS + i];
    for (int b = 0; b < NC; b++) hist[tid][b] = 0;
    __syncthreads();

#pragma unroll
    for (int k = 0; k < NS / 128; k++) {
        int i = tid * (NS / 128) + k;
        hist[tid][sbuck[i]]++;
    }
    __syncthreads();

    if (tid < NC) {
        int s = 0;
        for (int t = 0; t < 128; t++) s += hist[t][tid];
        tot[tid] = s;
    }
    __syncthreads();
    if (tid == 0) {
        int run = 0;
        for (int b = 0; b < NC; b++) { base[b] = run; run += tot[b]; }
    }
    __syncthreads();
    if (tid < NC) {
        int run = base[tid];
        for (int t = 0; t < 128; t++) {
            int c = hist[t][tid];
            hist[t][tid] = (unsigned short)run;
            run += c;
        }
    }
    __syncthreads();

#pragma unroll
    for (int k = 0; k < NS / 128; k++) {
        int i = tid * (NS / 128) + k;
        int b = sbuck[i];
        int pos = hist[tid][b]++;
        g_sticker[bh * NS + pos] = i;
    }
}

// ---------------- chunked attention: 16 queries x 32 keys per block -----------
__global__ __launch_bounds__(512)
void attn_kernel()
{
    const int c  = blockIdx.x;
    const int bh = blockIdx.y;

    __shared__ float kq[32][33];
    __shared__ float vv[32][33];
    __shared__ float rn[32];
    __shared__ int   nn[32];
    __shared__ int   hh[32];

    const int tid  = threadIdx.x;
    const int warp = tid >> 5;
    const int lane = tid & 31;

    if (tid < 32) {
        int cj   = (tid < BKTS) ? c : (c + NC - 1) % NC;
        int slot = cj * BKTS + (tid & (BKTS - 1));
        int item = g_sticker[bh * NS + slot];
        int n    = item % NPAD;
        nn[tid] = n;
        hh[tid] = item / NPAD;
    }
    __syncthreads();

    for (int idx = tid; idx < 32 * EDIM; idx += 512) {
        int j = idx >> 5, e = idx & 31;
        int off = (bh * NPAD + nn[j]) * EDIM + e;
        kq[j][e] = g_qk[off];
        vv[j][e] = g_v[off];
    }
    __syncthreads();

    if (tid < 32) {
        float s = 0.f;
#pragma unroll
        for (int e = 0; e < EDIM; e++) { float x = kq[tid][e]; s += x * x; }
        s = sqrtf(s);
        rn[tid] = 1.0f / fmaxf(s, 1e-12f);
    }
    __syncthreads();

    const int i = warp;
    const int j = lane;

    float d = 0.f;
#pragma unroll
    for (int e = 0; e < EDIM; e++) d += kq[i][e] * kq[j][e];
    d = d * rn[j] * 0.17677669529663687f;
    if (nn[i] == nn[j]) d = -50000.0f;

    float m = d;
#pragma unroll
    for (int o = 16; o > 0; o >>= 1) m = fmaxf(m, __shfl_xor_sync(0xffffffffu, m, o));
    float ex = expf(d - m);
    float sum = ex;
#pragma unroll
    for (int o = 16; o > 0; o >>= 1) sum += __shfl_xor_sync(0xffffffffu, sum, o);
    float lse = m + logf(sum);
    float p = ex / sum;

    float accv = 0.f;
#pragma unroll
    for (int jj = 0; jj < 32; jj++) {
        float pj = __shfl_sync(0xffffffffu, p, jj);
        accv += pj * vv[jj][lane];
    }

    int n_i = nn[i], h_i = hh[i];
    g_o[((bh * NH + h_i) * NPAD + n_i) * EDIM + lane] = accv;
    if (lane == 0) g_lse[(bh * NH + h_i) * NPAD + n_i] = lse;
}

// ---------------- combine hashes: softmax over per-hash lse -------------------
__global__ __launch_bounds__(256)
void combine_kernel()
{
    int gid  = blockIdx.x * blockDim.x + threadIdx.x;
    int wid  = gid >> 5;
    int lane = gid & 31;
    if (wid >= BH * NPAD) return;
    int bh = wid / NPAD;
    int n  = wid - bh * NPAD;

    float l0 = g_lse[(bh * NH + 0) * NPAD + n];
    float l1 = g_lse[(bh * NH + 1) * NPAD + n];
    float l2 = g_lse[(bh * NH + 2) * NPAD + n];
    float l3 = g_lse[(bh * NH + 3) * NPAD + n];
    float m = fmaxf(fmaxf(l0, l1), fmaxf(l2, l3));
    float e0 = expf(l0 - m), e1 = expf(l1 - m), e2 = expf(l2 - m), e3 = expf(l3 - m);
    float inv = 1.0f / (e0 + e1 + e2 + e3);

    float acc =
        e0 * inv * g_o[((bh * NH + 0) * NPAD + n) * EDIM + lane] +
        e1 * inv * g_o[((bh * NH + 1) * NPAD + n) * EDIM + lane] +
        e2 * inv * g_o[((bh * NH + 2) * NPAD + n) * EDIM + lane] +
        e3 * inv * g_o[((bh * NH + 3) * NPAD + n) * EDIM + lane];

    int b_l = bh >> 3, head = bh & 7;
    g_hcomb[(b_l * NPAD + n) * D + head * EDIM + lane] = acc;
}

// ---------------- launch ------------------------------------------------------
extern "C" void kernel_launch(void* const* d_in, const int* in_sizes, int n_in,
                              void* d_out, int out_size)
{
    const float* x      = (const float*)d_in[0];
    const float* ste    = (const float*)d_in[1];
    const float* w_proj = (const float*)d_in[2];
    const float* b_proj = (const float*)d_in[3];
    const float* w_qk   = (const float*)d_in[4];
    const float* w_v    = (const float*)d_in[5];
    const float* w_out  = (const float*)d_in[6];
    const float* b_out  = (const float*)d_in[7];
    const float* rots   = (const float*)d_in[8];
    float* out = (float*)d_out;

    gemm_k<0><<<dim3(MROWS / 128, 256 / 128), 256>>>(x, ste, w_proj, nullptr, b_proj, nullptr);
    gemm_k<1><<<dim3(MROWS / 128, 512 / 128), 256>>>(nullptr, nullptr, w_qk, w_v, nullptr, nullptr);
    hash_kernel<<<(BH * NPAD + 255) / 256, 256>>>(rots);
    sort_kernel<<<BH, 128>>>();
    attn_kernel<<<dim3(NC, BH), 512>>>();
    combine_kernel<<<(BH * NPAD * 32) / 256, 256>>>();
    gemm_k<2><<<dim3(MROWS / 128, 256 / 128), 256>>>(nullptr, nullptr, w_out, nullptr, b_out, out);
}

// round 4
// speedup vs baseline: 1.2469x; 1.0491x over previous
#include <cuda_runtime.h>
#include <math.h>

#define B_L   192
#define NVAL  325
#define NPAD  352
#define D     256
#define DPOS  64
#define KPROJ 320
#define HEADS 8
#define EDIM  32
#define BH    (B_L*HEADS)      /* 1536 */
#define NH    4
#define NB    22
#define NC    (NH*NB)          /* 88 */
#define BKTS  16
#define NS    (NH*NPAD)        /* 1408 */
#define MROWS (B_L*NPAD)       /* 67584 */

typedef unsigned long long u64;

__device__ __forceinline__ u64 pack2(float x, float y) {
    u64 r; asm("mov.b64 %0,{%1,%2};" : "=l"(r) : "f"(x), "f"(y)); return r;
}
__device__ __forceinline__ void unpack2(u64 v, float& x, float& y) {
    asm("mov.b64 {%0,%1},%2;" : "=f"(x), "=f"(y) : "l"(v));
}
__device__ __forceinline__ u64 fma2(u64 a, u64 b, u64 c) {
    u64 d; asm("fma.rn.f32x2 %0,%1,%2,%3;" : "=l"(d) : "l"(a), "l"(b), "l"(c)); return d;
}

// ---------------- scratch (static device allocations; no cudaMalloc) ----------
__device__ __align__(16) float g_h    [B_L*NPAD*D];
__device__ __align__(16) float g_qk   [BH*NPAD*EDIM];
__device__ __align__(16) float g_v    [BH*NPAD*EDIM];
__device__ int   g_bucket [BH*NS];
__device__ int   g_sticker[BH*NS];
__device__ __align__(16) float g_o    [BH*NH*NPAD*EDIM];
__device__ float g_lse  [BH*NH*NPAD];
__device__ __align__(16) float g_hcomb[B_L*NPAD*D];

// -------- 128x128 SGEMM, BK=8, 8x8/thread in 2x2 quadrants, FFMA2 -------------
// MODE 0: h = [x|ste] @ w_proj + b_proj   (M=67584, K=320, N=256) -> g_h (pad rows 0)
// MODE 1: [qk|v] = g_h @ [w_qk|w_v]       (M=67584, K=256, N=512) -> g_qk/g_v
// MODE 2: out = g_hcomb @ w_out + b_out   (M=67584, K=256, N=256) -> d_out (n<325 only)
template<int MODE>
__global__ __launch_bounds__(256, 2)
void gemm_k(const float* __restrict__ P0, const float* __restrict__ P1,
            const float* __restrict__ W0, const float* __restrict__ W1,
            const float* __restrict__ bias, float* __restrict__ Cout)
{
    constexpr int BM = 128, BN = 128, BK = 8;
    constexpr int KDIM = (MODE == 0) ? KPROJ : 256;
    constexpr int NT   = KDIM / BK;
    constexpr int LDA  = BM + 4;

    __shared__ float As[2][BK][LDA];
    __shared__ float Bs[2][BK][BN];

    const int tid = threadIdx.x;
    const int bm  = blockIdx.x * BM;
    const int bn  = blockIdx.y * BN;

    // gmem load mapping (unchanged)
    const int arow  = tid >> 1;
    const int akoff = (tid & 1) * 4;
    const int bk    = tid >> 5;
    const int bcol  = (tid & 31) * 4;

    const int r = bm + arow;
    long baseA, baseS = 0;
    bool validA = true;
    if (MODE == 0) {
        int b_l = r / NPAD;
        int n   = r - b_l * NPAD;
        validA  = (n < NVAL);
        long rr = (long)b_l * NVAL + n;
        baseA = rr * D;
        baseS = rr * DPOS;
    } else {
        baseA = (long)r * D;
    }

    const float* Wp;
    int wcolbase;
    if (MODE == 1 && bn >= 256) { Wp = W1; wcolbase = bn - 256; }
    else                         { Wp = W0; wcolbase = bn; }

    float4 aReg, bReg;

    auto load_gmem = [&](int kt) {
        int kk = kt + akoff;
        if (MODE == 0) {
            if (!validA) aReg = make_float4(0.f, 0.f, 0.f, 0.f);
            else if (kk < D) aReg = *(const float4*)(P0 + baseA + kk);
            else             aReg = *(const float4*)(P1 + baseS + (kk - D));
        } else if (MODE == 1) {
            aReg = *(const float4*)(g_h + baseA + kk);
        } else {
            aReg = *(const float4*)(g_hcomb + baseA + kk);
        }
        bReg = *(const float4*)(Wp + (long)(kt + bk) * D + wcolbase + bcol);
    };
    auto store_smem = [&](int buf) {
        As[buf][akoff + 0][arow] = aReg.x;
        As[buf][akoff + 1][arow] = aReg.y;
        As[buf][akoff + 2][arow] = aReg.z;
        As[buf][akoff + 3][arow] = aReg.w;
        *(float4*)(&Bs[buf][bk][bcol]) = bReg;
    };

    // quadrant micro-tile: rows {ty*4+i, 64+ty*4+i}, cols {tx*4.., 64+tx*4..}
    const int ty = tid >> 4;    // 0..15
    const int tx = tid & 15;    // 0..15

    // acc2[gi][gj][i][q]: gi=row quad, gj=col quad, i=row 0..3, q=col pair 0..1
    u64 acc2[2][2][4][2];
#pragma unroll
    for (int gi = 0; gi < 2; gi++)
#pragma unroll
        for (int gj = 0; gj < 2; gj++)
#pragma unroll
            for (int i = 0; i < 4; i++) {
                acc2[gi][gj][i][0] = 0ULL;
                acc2[gi][gj][i][1] = 0ULL;
            }

    load_gmem(0);
    store_smem(0);
    __syncthreads();

    int buf = 0;
    for (int t = 0; t < NT; ++t) {
        if (t + 1 < NT) load_gmem((t + 1) * BK);
#pragma unroll
        for (int k = 0; k < BK; k++) {
            float4 a0 = *(const float4*)(&As[buf][k][ty * 4]);
            float4 a1 = *(const float4*)(&As[buf][k][64 + ty * 4]);
            float4 b0 = *(const float4*)(&Bs[buf][k][tx * 4]);
            float4 b1 = *(const float4*)(&Bs[buf][k][64 + tx * 4]);
            u64 bp[2][2] = {{pack2(b0.x, b0.y), pack2(b0.z, b0.w)},
                            {pack2(b1.x, b1.y), pack2(b1.z, b1.w)}};
            float av[2][4] = {{a0.x, a0.y, a0.z, a0.w}, {a1.x, a1.y, a1.z, a1.w}};
#pragma unroll
            for (int gi = 0; gi < 2; gi++)
#pragma unroll
                for (int i = 0; i < 4; i++) {
                    u64 ap = pack2(av[gi][i], av[gi][i]);
#pragma unroll
                    for (int gj = 0; gj < 2; gj++) {
                        acc2[gi][gj][i][0] = fma2(ap, bp[gj][0], acc2[gi][gj][i][0]);
                        acc2[gi][gj][i][1] = fma2(ap, bp[gj][1], acc2[gi][gj][i][1]);
                    }
                }
        }
        if (t + 1 < NT) {
            store_smem(buf ^ 1);
            __syncthreads();
            buf ^= 1;
        }
    }

    // ---- epilogue ----
#pragma unroll
    for (int gi = 0; gi < 2; gi++)
#pragma unroll
    for (int i = 0; i < 4; i++) {
        int ro = bm + gi * 64 + ty * 4 + i;
#pragma unroll
        for (int gj = 0; gj < 2; gj++) {
            int cb = bn + gj * 64 + tx * 4;   // 4-aligned col base
            float c0, c1, c2, c3;
            unpack2(acc2[gi][gj][i][0], c0, c1);
            unpack2(acc2[gi][gj][i][1], c2, c3);

            if (MODE == 0) {
                int n = ro % NPAD;
                float4 v;
                if (n < NVAL)
                    v = make_float4(c0 + bias[cb + 0], c1 + bias[cb + 1],
                                    c2 + bias[cb + 2], c3 + bias[cb + 3]);
                else
                    v = make_float4(0.f, 0.f, 0.f, 0.f);
                *(float4*)(g_h + (long)ro * D + cb) = v;
            } else if (MODE == 1) {
                int b_l = ro / NPAD;
                int n   = ro - b_l * NPAD;
                int cc = cb;
                float* dst;
                if (cc < D) { int head = cc >> 5; int e = cc & 31;
                    dst = g_qk + ((long)((b_l << 3) + head) * NPAD + n) * EDIM + e; }
                else { cc -= D; int head = cc >> 5; int e = cc & 31;
                    dst = g_v  + ((long)((b_l << 3) + head) * NPAD + n) * EDIM + e; }
                *(float4*)(dst) = make_float4(c0, c1, c2, c3);
            } else {
                int b_l = ro / NPAD;
                int n   = ro - b_l * NPAD;
                if (n < NVAL) {
                    long off = ((long)b_l * NVAL + n) * D + cb;
                    *(float4*)(Cout + off) =
                        make_float4(c0 + bias[cb + 0], c1 + bias[cb + 1],
                                    c2 + bias[cb + 2], c3 + bias[cb + 3]);
                }
            }
        }
    }
}

// ---------------- hashing: rot = qk @ rotations, argmax over [rot,-rot] -------
__global__ __launch_bounds__(256)
void hash_kernel(const float* __restrict__ rot)
{
    __shared__ u64 srot2[EDIM][NH][6];
    int tid = threadIdx.x;
    for (int i = tid; i < EDIM * NH * 6; i += blockDim.x) {
        int e  = i / (NH * 6);
        int h  = (i / 6) % NH;
        int rr = i % 6;
        int r0 = 2 * rr, r1 = 2 * rr + 1;
        float x = (r0 < NB / 2) ? rot[(e * NH + h) * (NB / 2) + r0] : 0.f;
        float y = (r1 < NB / 2) ? rot[(e * NH + h) * (NB / 2) + r1] : 0.f;
        srot2[e][h][rr] = pack2(x, y);
    }
    __syncthreads();

    int gid = blockIdx.x * blockDim.x + tid;
    if (gid >= BH * NPAD) return;
    int bh = gid / NPAD;
    int n  = gid - bh * NPAD;

    float q[EDIM];
    const float* qp = &g_qk[(bh * NPAD + n) * EDIM];
#pragma unroll
    for (int e = 0; e < EDIM; e += 4) {
        float4 t = *(const float4*)(qp + e);
        q[e] = t.x; q[e + 1] = t.y; q[e + 2] = t.z; q[e + 3] = t.w;
    }

    for (int h = 0; h < NH; h++) {
        u64 s2[6];
#pragma unroll
        for (int rr = 0; rr < 6; rr++) s2[rr] = 0ULL;
#pragma unroll
        for (int e = 0; e < EDIM; e++) {
            u64 qq = pack2(q[e], q[e]);
#pragma unroll
            for (int rr = 0; rr < 6; rr++)
                s2[rr] = fma2(qq, srot2[e][h][rr], s2[rr]);
        }
        float rv[12];
#pragma unroll
        for (int rr = 0; rr < 6; rr++) unpack2(s2[rr], rv[2 * rr], rv[2 * rr + 1]);

        float best = rv[0];
        int bi = 0;
#pragma unroll
        for (int r = 1; r < NB / 2; r++)
            if (rv[r] > best) { best = rv[r]; bi = r; }
#pragma unroll
        for (int r = 0; r < NB / 2; r++)
            if (-rv[r] > best) { best = -rv[r]; bi = r + NB / 2; }
        g_bucket[bh * NS + h * NPAD + n] = bi + h * NB;
    }
}

// ---------------- stable counting sort per bh (88 buckets, 1408 items) --------
__global__ __launch_bounds__(128)
void sort_kernel()
{
    const int bh  = blockIdx.x;
    const int tid = threadIdx.x;

    __shared__ unsigned short hist[128][89];
    __shared__ int sbuck[NS];
    __shared__ int base[NC];
    __shared__ int tot[NC];

    for (int i = tid; i < NS; i += 128) sbuck[i] = g_bucket[bh * NS + i];
    for (int b = 0; b < NC; b++) hist[tid][b] = 0;
    __syncthreads();

#pragma unroll
    for (int k = 0; k < NS / 128; k++) {
        int i = tid * (NS / 128) + k;
        hist[tid][sbuck[i]]++;
    }
    __syncthreads();

    if (tid < NC) {
        int s = 0;
        for (int t = 0; t < 128; t++) s += hist[t][tid];
        tot[tid] = s;
    }
    __syncthreads();
    if (tid == 0) {
        int run = 0;
        for (int b = 0; b < NC; b++) { base[b] = run; run += tot[b]; }
    }
    __syncthreads();
    if (tid < NC) {
        int run = base[tid];
        for (int t = 0; t < 128; t++) {
            int c = hist[t][tid];
            hist[t][tid] = (unsigned short)run;
            run += c;
        }
    }
    __syncthreads();

#pragma unroll
    for (int k = 0; k < NS / 128; k++) {
        int i = tid * (NS / 128) + k;
        int b = sbuck[i];
        int pos = hist[tid][b]++;
        g_sticker[bh * NS + pos] = i;
    }
}

// ---------------- chunked attention: 16 queries x 32 keys per block -----------
__global__ __launch_bounds__(512)
void attn_kernel()
{
    const int c  = blockIdx.x;
    const int bh = blockIdx.y;

    __shared__ float kq[32][33];
    __shared__ float vv[32][33];
    __shared__ float rn[32];
    __shared__ int   nn[32];
    __shared__ int   hh[32];

    const int tid  = threadIdx.x;
    const int warp = tid >> 5;
    const int lane = tid & 31;

    if (tid < 32) {
        int cj   = (tid < BKTS) ? c : (c + NC - 1) % NC;
        int slot = cj * BKTS + (tid & (BKTS - 1));
        int item = g_sticker[bh * NS + slot];
        int n    = item % NPAD;
        nn[tid] = n;
        hh[tid] = item / NPAD;
    }
    __syncthreads();

    for (int idx = tid; idx < 32 * EDIM; idx += 512) {
        int j = idx >> 5, e = idx & 31;
        int off = (bh * NPAD + nn[j]) * EDIM + e;
        kq[j][e] = g_qk[off];
        vv[j][e] = g_v[off];
    }
    __syncthreads();

    if (tid < 32) {
        float s = 0.f;
#pragma unroll
        for (int e = 0; e < EDIM; e++) { float x = kq[tid][e]; s += x * x; }
        s = sqrtf(s);
        rn[tid] = 1.0f / fmaxf(s, 1e-12f);
    }
    __syncthreads();

    const int i = warp;
    const int j = lane;

    float d = 0.f;
#pragma unroll
    for (int e = 0; e < EDIM; e++) d += kq[i][e] * kq[j][e];
    d = d * rn[j] * 0.17677669529663687f;
    if (nn[i] == nn[j]) d = -50000.0f;

    float m = d;
#pragma unroll
    for (int o = 16; o > 0; o >>= 1) m = fmaxf(m, __shfl_xor_sync(0xffffffffu, m, o));
    float ex = expf(d - m);
    float sum = ex;
#pragma unroll
    for (int o = 16; o > 0; o >>= 1) sum += __shfl_xor_sync(0xffffffffu, sum, o);
    float lse = m + logf(sum);
    float p = ex / sum;

    float accv = 0.f;
#pragma unroll
    for (int jj = 0; jj < 32; jj++) {
        float pj = __shfl_sync(0xffffffffu, p, jj);
        accv += pj * vv[jj][lane];
    }

    int n_i = nn[i], h_i = hh[i];
    g_o[((bh * NH + h_i) * NPAD + n_i) * EDIM + lane] = accv;
    if (lane == 0) g_lse[(bh * NH + h_i) * NPAD + n_i] = lse;
}

// ---------------- combine hashes: softmax over per-hash lse -------------------
__global__ __launch_bounds__(256)
void combine_kernel()
{
    int gid  = blockIdx.x * blockDim.x + threadIdx.x;
    int wid  = gid >> 5;
    int lane = gid & 31;
    if (wid >= BH * NPAD) return;
    int bh = wid / NPAD;
    int n  = wid - bh * NPAD;

    float l0 = g_lse[(bh * NH + 0) * NPAD + n];
    float l1 = g_lse[(bh * NH + 1) * NPAD + n];
    float l2 = g_lse[(bh * NH + 2) * NPAD + n];
    float l3 = g_lse[(bh * NH + 3) * NPAD + n];
    float m = fmaxf(fmaxf(l0, l1), fmaxf(l2, l3));
    float e0 = expf(l0 - m), e1 = expf(l1 - m), e2 = expf(l2 - m), e3 = expf(l3 - m);
    float inv = 1.0f / (e0 + e1 + e2 + e3);

    float acc =
        e0 * inv * g_o[((bh * NH + 0) * NPAD + n) * EDIM + lane] +
        e1 * inv * g_o[((bh * NH + 1) * NPAD + n) * EDIM + lane] +
        e2 * inv * g_o[((bh * NH + 2) * NPAD + n) * EDIM + lane] +
        e3 * inv * g_o[((bh * NH + 3) * NPAD + n) * EDIM + lane];

    int b_l = bh >> 3, head = bh & 7;
    g_hcomb[(b_l * NPAD + n) * D + head * EDIM + lane] = acc;
}

// ---------------- launch ------------------------------------------------------
extern "C" void kernel_launch(void* const* d_in, const int* in_sizes, int n_in,
                              void* d_out, int out_size)
{
    const float* x      = (const float*)d_in[0];
    const float* ste    = (const float*)d_in[1];
    const float* w_proj = (const float*)d_in[2];
    const float* b_proj = (const float*)d_in[3];
    const float* w_qk   = (const float*)d_in[4];
    const float* w_v    = (const float*)d_in[5];
    const float* w_out  = (const float*)d_in[6];
    const float* b_out  = (const float*)d_in[7];
    const float* rots   = (const float*)d_in[8];
    float* out = (float*)d_out;

    gemm_k<0><<<dim3(MROWS / 128, 256 / 128), 256>>>(x, ste, w_proj, nullptr, b_proj, nullptr);
    gemm_k<1><<<dim3(MROWS / 128, 512 / 128), 256>>>(nullptr, nullptr, w_qk, w_v, nullptr, nullptr);
    hash_kernel<<<(BH * NPAD + 255) / 256, 256>>>(rots);
    sort_kernel<<<BH, 128>>>();
    attn_kernel<<<dim3(NC, BH), 512>>>();
    combine_kernel<<<(BH * NPAD * 32) / 256, 256>>>();
    gemm_k<2><<<dim3(MROWS / 128, 256 / 128), 256>>>(nullptr, nullptr, w_out, nullptr, b_out, out);
}